// round 9
// baseline (speedup 1.0000x reference)
#include <cuda_runtime.h>

// CTC greedy search — two kernels (proven fastest structure, R2).
// R9: max_total folded into K1 via RED.F32 atomics; K2 is int-only.
//   logits: (T=2048, N=32, V=1024) float32, batch_first = False
//   in_lens: (N,) int (int32 or int64 — detected at runtime)
// Output (float32): [ max_total (N) | paths (T*N, t*N+n) | out_lens (N) ]

#define T_DIM 2048
#define N_DIM 32
#define V_DIM 1024
#define BLANK 1023   // (-1 + V) % V

// Scratch (allocation-free rule: __device__ globals; zero-init at load).
__device__ int   g_amax[(size_t)T_DIM * N_DIM];   // n-major for K2 coalescing
__device__ float g_maxsum[N_DIM];                 // atomic accumulators

// ---------------------------------------------------------------------------
// Kernel 1: one warp per (t, n) row of V=1024 logits (~6.5-6.7 TB/s).
// Epilogue: amax store, paths default store, RED.F32 of -log(sum) if t < L.
// ---------------------------------------------------------------------------
__global__ void __launch_bounds__(256) ctc_rowmax_kernel(
    const float* __restrict__ logits,
    const void* __restrict__ in_lens_raw,
    float* __restrict__ out_paths)
{
    const int warp_id = (blockIdx.x * 256 + threadIdx.x) >> 5;  // = t*N + n
    const int lane = threadIdx.x & 31;

    const float4* row =
        reinterpret_cast<const float4*>(logits) + (size_t)warp_id * (V_DIM / 4);

    float4 v[8];
#pragma unroll
    for (int k = 0; k < 8; k++) v[k] = row[lane + 32 * k];

    // per-lane max + first-occurrence argmax
    float m = -1e30f; int mi = 0;
#pragma unroll
    for (int k = 0; k < 8; k++) {
        const int base = (lane + 32 * k) * 4;
        float x;
        x = v[k].x; if (x > m) { m = x; mi = base;     }
        x = v[k].y; if (x > m) { m = x; mi = base + 1; }
        x = v[k].z; if (x > m) { m = x; mi = base + 2; }
        x = v[k].w; if (x > m) { m = x; mi = base + 3; }
    }
#pragma unroll
    for (int off = 16; off; off >>= 1) {
        float om = __shfl_down_sync(0xffffffffu, m, off);
        int  omi = __shfl_down_sync(0xffffffffu, mi, off);
        if (om > m || (om == m && omi < mi)) { m = om; mi = omi; }
    }
    m  = __shfl_sync(0xffffffffu, m, 0);
    mi = __shfl_sync(0xffffffffu, mi, 0);

    float s = 0.f;
#pragma unroll
    for (int k = 0; k < 8; k++) {
        s += __expf(v[k].x - m) + __expf(v[k].y - m)
           + __expf(v[k].z - m) + __expf(v[k].w - m);
    }
#pragma unroll
    for (int off = 16; off; off >>= 1) s += __shfl_down_sync(0xffffffffu, s, off);

    if (lane == 0) {
        const int t = warp_id >> 5;          // / N_DIM
        const int n = warp_id & 31;
        g_amax[n * T_DIM + t] = mi;
        out_paths[warp_id] = (float)mi;      // masked_scatter default region

        // dtype-robust in_lens (values in [1,T]; int64 LE => high words 0)
        const int* w32 = (const int*)in_lens_raw;
        const int L = (w32[1] == 0) ? (int)((const long long*)in_lens_raw)[n]
                                    : w32[n];
        if (t < L) atomicAdd(&g_maxsum[n], -logf(s));   // RED.F32, no return use
    }
}

// ---------------------------------------------------------------------------
// Kernel 2: one 1024-thread block per batch row; int-only single-pass scan.
// Each thread owns 2 consecutive t's (one int2 load).
// ---------------------------------------------------------------------------
__global__ void __launch_bounds__(1024) ctc_scan_kernel(
    const void* __restrict__ in_lens_raw, float* __restrict__ out)
{
    const int n    = blockIdx.x;
    const int tid  = threadIdx.x;     // 0..1023
    const int lane = tid & 31;
    const int wid  = tid >> 5;        // 0..31

    // max_total: read accumulator, publish, reset for next graph replay.
    if (tid == 0) {
        out[n] = g_maxsum[n];
        g_maxsum[n] = 0.f;
    }

    // dtype-robust in_lens
    const int* w32 = (const int*)in_lens_raw;
    const bool is64 = (w32[1] == 0);
    const int L = is64 ? (int)((const long long*)in_lens_raw)[n] : w32[n];

    const int* a = g_amax + n * T_DIM;

    const int t0 = 2 * tid;
    const int2 aa = reinterpret_cast<const int2*>(a)[tid];

    int prev = __shfl_up_sync(0xffffffffu, aa.y, 1);
    if (lane == 0) prev = (tid == 0) ? -123 : a[t0 - 1];

    const bool k0 = (aa.x != BLANK) && (aa.x != prev) && (t0     < L);
    const bool k1 = (aa.y != BLANK) && (aa.y != aa.x) && (t0 + 1 < L);
    const int  cnt = (int)k0 + (int)k1;

    // inclusive warp scan of cnt
    int inc = cnt;
#pragma unroll
    for (int off = 1; off < 32; off <<= 1) {
        int v = __shfl_up_sync(0xffffffffu, inc, off);
        if (lane >= off) inc += v;
    }

    __shared__ int s_wcnt[32];
    if (lane == 31) s_wcnt[wid] = inc;      // warp total
    __syncthreads();

    if (wid == 0) {
        int v = s_wcnt[lane];
        int inc2 = v;
#pragma unroll
        for (int off = 1; off < 32; off <<= 1) {
            int u = __shfl_up_sync(0xffffffffu, inc2, off);
            if (lane >= off) inc2 += u;
        }
        s_wcnt[lane] = inc2 - v;            // exclusive warp offset
        if (lane == 31)
            out[N_DIM + (size_t)T_DIM * N_DIM + n] = (float)inc2;  // out_lens
    }
    __syncthreads();

    // scatter kept tokens
    float* paths = out + N_DIM;
    int pos = s_wcnt[wid] + (inc - cnt);
    if (k0) { paths[pos * N_DIM + n] = (float)aa.x; pos++; }
    if (k1) { paths[pos * N_DIM + n] = (float)aa.y; }
}

// ---------------------------------------------------------------------------
extern "C" void kernel_launch(void* const* d_in, const int* in_sizes, int n_in,
                              void* d_out, int out_size)
{
    const float* logits = (const float*)d_in[0];
    const void*  lens   = d_in[1];
    float* out = (float*)d_out;

    (void)in_sizes; (void)n_in; (void)out_size;

    // Kernel 1: T*N = 65536 warps -> 8192 blocks of 256 threads
    ctc_rowmax_kernel<<<(T_DIM * N_DIM) / 8, 256>>>(logits, lens, out + N_DIM);
    // Kernel 2: one 1024-thread block per batch row, int-only single pass
    ctc_scan_kernel<<<N_DIM, 1024>>>(lens, out);
}

// round 10
// speedup vs baseline: 1.0742x; 1.0742x over previous
#include <cuda_runtime.h>

// CTC greedy search — ONE launch: 8192 streaming blocks (R2's exact t-major
// mapping, proven 6.5-6.8 TB/s) + 32 trailing scan blocks that the CTA
// scheduler starts last; they spin on a done-counter through K1's tail.
//   logits: (T=2048, N=32, V=1024) float32, batch_first = False
//   in_lens: (N,) int (int32 or int64 — detected at runtime)
// Output (float32): [ max_total (N) | paths (T*N, t*N+n) | out_lens (N) ]

#define T_DIM 2048
#define N_DIM 32
#define V_DIM 1024
#define BLANK 1023   // (-1 + V) % V
#define P1_BLOCKS 8192          // (T*N)/8 streaming blocks
#define GRID_B (P1_BLOCKS + N_DIM)

// Scratch (allocation-free rule: __device__ globals; zero-init at load).
__device__ int   g_amax[(size_t)T_DIM * N_DIM];   // n-major for scan coalescing
__device__ float g_maxv[(size_t)T_DIM * N_DIM];
__device__ int   g_done;   // phase-1 blocks completed
__device__ int   g_ack;    // scan blocks completed (for replay-safe reset)

__global__ void __launch_bounds__(256) ctc_all_kernel(
    const float* __restrict__ logits,
    const void* __restrict__ in_lens_raw,
    float* __restrict__ out)
{
    const int tid  = threadIdx.x;
    const int lane = tid & 31;
    const int wid  = tid >> 5;

    float* out_paths = out + N_DIM;

    if (blockIdx.x < P1_BLOCKS) {
        // =================================================================
        // Phase 1 (R2's K1, unchanged): warp_id = t*N + n, sequential.
        // =================================================================
        const int warp_id = blockIdx.x * 8 + wid;

        const float4* row = reinterpret_cast<const float4*>(logits)
                          + (size_t)warp_id * (V_DIM / 4);

        float4 v[8];
#pragma unroll
        for (int k = 0; k < 8; k++) v[k] = row[lane + 32 * k];

        float m = -1e30f; int mi = 0;
#pragma unroll
        for (int k = 0; k < 8; k++) {
            const int base = (lane + 32 * k) * 4;
            float x;
            x = v[k].x; if (x > m) { m = x; mi = base;     }
            x = v[k].y; if (x > m) { m = x; mi = base + 1; }
            x = v[k].z; if (x > m) { m = x; mi = base + 2; }
            x = v[k].w; if (x > m) { m = x; mi = base + 3; }
        }
#pragma unroll
        for (int off = 16; off; off >>= 1) {
            float om = __shfl_down_sync(0xffffffffu, m, off);
            int  omi = __shfl_down_sync(0xffffffffu, mi, off);
            if (om > m || (om == m && omi < mi)) { m = om; mi = omi; }
        }
        m  = __shfl_sync(0xffffffffu, m, 0);
        mi = __shfl_sync(0xffffffffu, mi, 0);

        float s = 0.f;
#pragma unroll
        for (int k = 0; k < 8; k++) {
            s += __expf(v[k].x - m) + __expf(v[k].y - m)
               + __expf(v[k].z - m) + __expf(v[k].w - m);
        }
#pragma unroll
        for (int off = 16; off; off >>= 1)
            s += __shfl_down_sync(0xffffffffu, s, off);

        if (lane == 0) {
            const int t = warp_id >> 5;          // / N_DIM
            const int n = warp_id & 31;
            g_amax[n * T_DIM + t] = mi;
            g_maxv[n * T_DIM + t] = -logf(s);    // max over V of log_softmax
            out_paths[warp_id] = (float)mi;      // masked_scatter default
        }

        // Release: one fence + one atomic per block.
        __syncthreads();
        if (tid == 0) {
            __threadfence();
            atomicAdd(&g_done, 1);
        }
        return;
    }

    // =====================================================================
    // Scan blocks (scheduled last): one per batch row. Spin through the
    // phase-1 tail, then single-pass dedup/compaction (8 t's per thread).
    // =====================================================================
    const int n = blockIdx.x - P1_BLOCKS;

    if (tid == 0) {
        while (atomicAdd(&g_done, 0) < P1_BLOCKS) __nanosleep(64);
        __threadfence();   // acquire
    }
    __syncthreads();

    __shared__ int   swc[8];
    __shared__ float sws[8];

    // dtype-robust in_lens: values in [1,T]; int64 LE => high words are 0.
    const int* w32 = (const int*)in_lens_raw;
    const bool is64 = (w32[1] == 0);
    const int L = is64 ? (int)((const long long*)in_lens_raw)[n] : w32[n];

    const int*   a  = g_amax + n * T_DIM;
    const float* mv = g_maxv + n * T_DIM;

    const int t0 = tid * 8;
    const int4 A0 = reinterpret_cast<const int4*>(a)[2 * tid];
    const int4 A1 = reinterpret_cast<const int4*>(a)[2 * tid + 1];
    const float4 M0 = reinterpret_cast<const float4*>(mv)[2 * tid];
    const float4 M1 = reinterpret_cast<const float4*>(mv)[2 * tid + 1];

    int av[8] = {A0.x, A0.y, A0.z, A0.w, A1.x, A1.y, A1.z, A1.w};

    int prev = __shfl_up_sync(0xffffffffu, A1.w, 1);
    if (lane == 0) prev = (tid == 0) ? -123 : a[t0 - 1];

    bool kf[8]; int cnt = 0; int p = prev;
#pragma unroll
    for (int i = 0; i < 8; i++) {
        kf[i] = (av[i] != BLANK) && (av[i] != p) && (t0 + i < L);
        p = av[i];
        cnt += (int)kf[i];
    }

    float loc = 0.f;
    loc += (t0 + 0 < L) ? M0.x : 0.f;
    loc += (t0 + 1 < L) ? M0.y : 0.f;
    loc += (t0 + 2 < L) ? M0.z : 0.f;
    loc += (t0 + 3 < L) ? M0.w : 0.f;
    loc += (t0 + 4 < L) ? M1.x : 0.f;
    loc += (t0 + 5 < L) ? M1.y : 0.f;
    loc += (t0 + 6 < L) ? M1.z : 0.f;
    loc += (t0 + 7 < L) ? M1.w : 0.f;

    int inc = cnt;
#pragma unroll
    for (int off = 1; off < 32; off <<= 1) {
        int v = __shfl_up_sync(0xffffffffu, inc, off);
        if (lane >= off) inc += v;
        loc += __shfl_down_sync(0xffffffffu, loc, off);
    }
    if (lane == 31) swc[wid] = inc;
    if (lane == 0)  sws[wid] = loc;
    __syncthreads();

    if (wid == 0) {
        int v = (lane < 8) ? swc[lane] : 0;
        int inc2 = v;
#pragma unroll
        for (int off = 1; off < 32; off <<= 1) {
            int u = __shfl_up_sync(0xffffffffu, inc2, off);
            if (lane >= off) inc2 += u;
        }
        if (lane < 8) swc[lane] = inc2 - v;          // exclusive warp offsets
        if (lane == 7)
            out[N_DIM + (size_t)T_DIM * N_DIM + n] = (float)inc2;  // out_lens

        float fs = (lane < 8) ? sws[lane] : 0.f;
#pragma unroll
        for (int off = 16; off; off >>= 1)
            fs += __shfl_down_sync(0xffffffffu, fs, off);
        if (lane == 0) out[n] = fs;                  // max_total
    }
    __syncthreads();

    int pos = swc[wid] + (inc - cnt);
#pragma unroll
    for (int i = 0; i < 8; i++) {
        if (kf[i]) { out_paths[pos * N_DIM + n] = (float)av[i]; pos++; }
    }

    // Ack; 32nd scan block resets counters for deterministic graph replay.
    __syncthreads();
    if (tid == 0) {
        int o = atomicAdd(&g_ack, 1);
        if (o == N_DIM - 1) {
            atomicExch(&g_done, 0);
            atomicExch(&g_ack, 0);
        }
    }
}

// ---------------------------------------------------------------------------
extern "C" void kernel_launch(void* const* d_in, const int* in_sizes, int n_in,
                              void* d_out, int out_size)
{
    const float* logits = (const float*)d_in[0];
    const void*  lens   = d_in[1];
    float* out = (float*)d_out;

    (void)in_sizes; (void)n_in; (void)out_size;

    ctc_all_kernel<<<GRID_B, 256>>>(logits, lens, out);
}

// round 11
// speedup vs baseline: 1.0770x; 1.0026x over previous
#include <cuda_runtime.h>

// CTC greedy search — ONE launch: 8192 streaming blocks (t-major mapping) +
// 32 trailing scan blocks. R11: release/acquire via scoped atomics
// (red.release / ld.acquire) — NO __threadfence anywhere: gpu-scope fence
// emits CCTL.IVALL (L1D flush) which we believe poisoned fused streaming BW.
//   logits: (T=2048, N=32, V=1024) float32, batch_first = False
//   in_lens: (N,) int (int32 or int64 — detected at runtime)
// Output (float32): [ max_total (N) | paths (T*N, t*N+n) | out_lens (N) ]

#define T_DIM 2048
#define N_DIM 32
#define V_DIM 1024
#define BLANK 1023   // (-1 + V) % V
#define P1_BLOCKS 8192          // (T*N)/8 streaming blocks
#define GRID_B (P1_BLOCKS + N_DIM)

// Scratch (allocation-free rule: __device__ globals; zero-init at load).
__device__ int   g_amax[(size_t)T_DIM * N_DIM];   // n-major for scan coalescing
__device__ float g_maxv[(size_t)T_DIM * N_DIM];
__device__ int   g_done;   // phase-1 blocks completed (release-published)
__device__ int   g_ack;    // scan blocks completed (replay-safe reset)

__device__ __forceinline__ void red_release_add(int* addr, int val) {
    asm volatile("red.release.gpu.global.add.s32 [%0], %1;"
                 :: "l"(addr), "r"(val) : "memory");
}
__device__ __forceinline__ int ld_acquire(int* addr) {
    int v;
    asm volatile("ld.acquire.gpu.global.s32 %0, [%1];"
                 : "=r"(v) : "l"(addr) : "memory");
    return v;
}

__global__ void __launch_bounds__(256) ctc_all_kernel(
    const float* __restrict__ logits,
    const void* __restrict__ in_lens_raw,
    float* __restrict__ out)
{
    const int tid  = threadIdx.x;
    const int lane = tid & 31;
    const int wid  = tid >> 5;

    float* out_paths = out + N_DIM;

    if (blockIdx.x < P1_BLOCKS) {
        // =================================================================
        // Phase 1: warp_id = t*N + n, sequential t-major mapping.
        // =================================================================
        const int warp_id = blockIdx.x * 8 + wid;

        const float4* row = reinterpret_cast<const float4*>(logits)
                          + (size_t)warp_id * (V_DIM / 4);

        float4 v[8];
#pragma unroll
        for (int k = 0; k < 8; k++) v[k] = row[lane + 32 * k];

        float m = -1e30f; int mi = 0;
#pragma unroll
        for (int k = 0; k < 8; k++) {
            const int base = (lane + 32 * k) * 4;
            float x;
            x = v[k].x; if (x > m) { m = x; mi = base;     }
            x = v[k].y; if (x > m) { m = x; mi = base + 1; }
            x = v[k].z; if (x > m) { m = x; mi = base + 2; }
            x = v[k].w; if (x > m) { m = x; mi = base + 3; }
        }
#pragma unroll
        for (int off = 16; off; off >>= 1) {
            float om = __shfl_down_sync(0xffffffffu, m, off);
            int  omi = __shfl_down_sync(0xffffffffu, mi, off);
            if (om > m || (om == m && omi < mi)) { m = om; mi = omi; }
        }
        m  = __shfl_sync(0xffffffffu, m, 0);
        mi = __shfl_sync(0xffffffffu, mi, 0);

        float s = 0.f;
#pragma unroll
        for (int k = 0; k < 8; k++) {
            s += __expf(v[k].x - m) + __expf(v[k].y - m)
               + __expf(v[k].z - m) + __expf(v[k].w - m);
        }
#pragma unroll
        for (int off = 16; off; off >>= 1)
            s += __shfl_down_sync(0xffffffffu, s, off);

        if (lane == 0) {
            const int t = warp_id >> 5;          // / N_DIM
            const int n = warp_id & 31;
            g_amax[n * T_DIM + t] = mi;
            g_maxv[n * T_DIM + t] = -logf(s);    // max over V of log_softmax
            out_paths[warp_id] = (float)mi;      // masked_scatter default
        }

        // Release: bar.sync (intra-block HB) + ONE scoped release-RED.
        // Cumulativity publishes all warps' STGs; no fence, no L1 flush.
        __syncthreads();
        if (tid == 0) red_release_add(&g_done, 1);
        return;
    }

    // =====================================================================
    // Scan blocks (scheduled last): one per batch row. Acquire-poll the
    // counter, then single-pass dedup/compaction (8 t's per thread).
    // =====================================================================
    const int n = blockIdx.x - P1_BLOCKS;

    if (tid == 0) {
        while (ld_acquire(&g_done) < P1_BLOCKS) __nanosleep(64);
    }
    __syncthreads();   // HB: tid0's acquire ordered before all threads' reads

    __shared__ int   swc[8];
    __shared__ float sws[8];

    // dtype-robust in_lens: values in [1,T]; int64 LE => high words are 0.
    const int* w32 = (const int*)in_lens_raw;
    const bool is64 = (w32[1] == 0);
    const int L = is64 ? (int)((const long long*)in_lens_raw)[n] : w32[n];

    const int*   a  = g_amax + n * T_DIM;
    const float* mv = g_maxv + n * T_DIM;

    const int t0 = tid * 8;
    const int4 A0 = reinterpret_cast<const int4*>(a)[2 * tid];
    const int4 A1 = reinterpret_cast<const int4*>(a)[2 * tid + 1];
    const float4 M0 = reinterpret_cast<const float4*>(mv)[2 * tid];
    const float4 M1 = reinterpret_cast<const float4*>(mv)[2 * tid + 1];

    int av[8] = {A0.x, A0.y, A0.z, A0.w, A1.x, A1.y, A1.z, A1.w};

    int prev = __shfl_up_sync(0xffffffffu, A1.w, 1);
    if (lane == 0) prev = (tid == 0) ? -123 : a[t0 - 1];

    bool kf[8]; int cnt = 0; int p = prev;
#pragma unroll
    for (int i = 0; i < 8; i++) {
        kf[i] = (av[i] != BLANK) && (av[i] != p) && (t0 + i < L);
        p = av[i];
        cnt += (int)kf[i];
    }

    float loc = 0.f;
    loc += (t0 + 0 < L) ? M0.x : 0.f;
    loc += (t0 + 1 < L) ? M0.y : 0.f;
    loc += (t0 + 2 < L) ? M0.z : 0.f;
    loc += (t0 + 3 < L) ? M0.w : 0.f;
    loc += (t0 + 4 < L) ? M1.x : 0.f;
    loc += (t0 + 5 < L) ? M1.y : 0.f;
    loc += (t0 + 6 < L) ? M1.z : 0.f;
    loc += (t0 + 7 < L) ? M1.w : 0.f;

    int inc = cnt;
#pragma unroll
    for (int off = 1; off < 32; off <<= 1) {
        int v = __shfl_up_sync(0xffffffffu, inc, off);
        if (lane >= off) inc += v;
        loc += __shfl_down_sync(0xffffffffu, loc, off);
    }
    if (lane == 31) swc[wid] = inc;
    if (lane == 0)  sws[wid] = loc;
    __syncthreads();

    if (wid == 0) {
        int v = (lane < 8) ? swc[lane] : 0;
        int inc2 = v;
#pragma unroll
        for (int off = 1; off < 32; off <<= 1) {
            int u = __shfl_up_sync(0xffffffffu, inc2, off);
            if (lane >= off) inc2 += u;
        }
        if (lane < 8) swc[lane] = inc2 - v;          // exclusive warp offsets
        if (lane == 7)
            out[N_DIM + (size_t)T_DIM * N_DIM + n] = (float)inc2;  // out_lens

        float fs = (lane < 8) ? sws[lane] : 0.f;
#pragma unroll
        for (int off = 16; off; off >>= 1)
            fs += __shfl_down_sync(0xffffffffu, fs, off);
        if (lane == 0) out[n] = fs;                  // max_total
    }
    __syncthreads();

    int pos = swc[wid] + (inc - cnt);
#pragma unroll
    for (int i = 0; i < 8; i++) {
        if (kf[i]) { out_paths[pos * N_DIM + n] = (float)av[i]; pos++; }
    }

    // Ack; 32nd scan block resets counters for deterministic graph replay.
    // (All scan blocks have finished polling g_done before the 32nd acks.)
    __syncthreads();
    if (tid == 0) {
        int o = atomicAdd(&g_ack, 1);
        if (o == N_DIM - 1) {
            atomicExch(&g_done, 0);
            atomicExch(&g_ack, 0);
        }
    }
}

// ---------------------------------------------------------------------------
extern "C" void kernel_launch(void* const* d_in, const int* in_sizes, int n_in,
                              void* d_out, int out_size)
{
    const float* logits = (const float*)d_in[0];
    const void*  lens   = d_in[1];
    float* out = (float*)d_out;

    (void)in_sizes; (void)n_in; (void)out_size;

    ctc_all_kernel<<<GRID_B, 256>>>(logits, lens, out);
}

// round 12
// speedup vs baseline: 1.1399x; 1.0584x over previous
#include <cuda_runtime.h>

// CTC greedy search — two kernels (R2 structure, best measured: 47.58us).
// R12: single isolated change vs R2 — __ldcs (evict-first) on the logits
// stream to keep K1's outputs resident in L2 for K2's dependent loads.
//   logits: (T=2048, N=32, V=1024) float32, batch_first = False
//   in_lens: (N,) int (int32 or int64 — detected at runtime)
// Output (float32): [ max_total (N) | paths (T*N, t*N+n) | out_lens (N) ]

#define T_DIM 2048
#define N_DIM 32
#define V_DIM 1024
#define BLANK 1023   // (-1 + V) % V

// Scratch (allocation-free rule: __device__ globals). n-major for kernel2 coalescing.
__device__ int   g_amax[(size_t)T_DIM * N_DIM];
__device__ float g_maxv[(size_t)T_DIM * N_DIM];

// ---------------------------------------------------------------------------
// Kernel 1: one warp per (t, n) row of V=1024 logits (~6.7 TB/s proven).
// ---------------------------------------------------------------------------
__global__ void __launch_bounds__(256) ctc_rowmax_kernel(
    const float* __restrict__ logits, float* __restrict__ out_paths)
{
    const int warp_id = (blockIdx.x * 256 + threadIdx.x) >> 5;  // = t*N + n
    const int lane = threadIdx.x & 31;

    const float4* row =
        reinterpret_cast<const float4*>(logits) + (size_t)warp_id * (V_DIM / 4);

    float4 v[8];
#pragma unroll
    for (int k = 0; k < 8; k++) v[k] = __ldcs(&row[lane + 32 * k]);  // evict-first

    // per-lane max + first-occurrence argmax (indices visited in increasing order)
    float m = -1e30f; int mi = 0;
#pragma unroll
    for (int k = 0; k < 8; k++) {
        const int base = (lane + 32 * k) * 4;
        float x;
        x = v[k].x; if (x > m) { m = x; mi = base;     }
        x = v[k].y; if (x > m) { m = x; mi = base + 1; }
        x = v[k].z; if (x > m) { m = x; mi = base + 2; }
        x = v[k].w; if (x > m) { m = x; mi = base + 3; }
    }
    // warp reduce (ties -> smaller global index == first occurrence)
#pragma unroll
    for (int off = 16; off; off >>= 1) {
        float om = __shfl_down_sync(0xffffffffu, m, off);
        int  omi = __shfl_down_sync(0xffffffffu, mi, off);
        if (om > m || (om == m && omi < mi)) { m = om; mi = omi; }
    }
    m  = __shfl_sync(0xffffffffu, m, 0);
    mi = __shfl_sync(0xffffffffu, mi, 0);

    // sum exp(x - m); MUFU throughput hides under HBM stream
    float s = 0.f;
#pragma unroll
    for (int k = 0; k < 8; k++) {
        s += __expf(v[k].x - m) + __expf(v[k].y - m)
           + __expf(v[k].z - m) + __expf(v[k].w - m);
    }
#pragma unroll
    for (int off = 16; off; off >>= 1) s += __shfl_down_sync(0xffffffffu, s, off);

    if (lane == 0) {
        const int t = warp_id >> 5;          // / N_DIM
        const int n = warp_id & 31;
        g_amax[n * T_DIM + t] = mi;
        g_maxv[n * T_DIM + t] = -logf(s);    // max over V of log_softmax
        out_paths[warp_id] = (float)mi;      // masked_scatter default region
    }
}

// ---------------------------------------------------------------------------
// Kernel 2 (single-pass): one 1024-thread block per batch row n.
// Each thread owns 2 consecutive timesteps (one int2 / float2 load).
//   * max_total[n] = sum_{t<L} maxlogp  (warp reduce + warp-0 reduce)
//   * keep flags -> one warp scan + warp-0 scan of warp totals -> compaction
// ---------------------------------------------------------------------------
__global__ void __launch_bounds__(1024) ctc_scan_kernel(
    const void* __restrict__ in_lens_raw, float* __restrict__ out)
{
    const int n    = blockIdx.x;
    const int tid  = threadIdx.x;     // 0..1023
    const int lane = tid & 31;
    const int wid  = tid >> 5;        // 0..31

    // dtype-robust in_lens read: values are in [1, T] (never 0). If the buffer
    // is int64 (LE), every high 32-bit word is 0; if int32, word[1] >= 1.
    const int* w32 = (const int*)in_lens_raw;
    const bool is64 = (w32[1] == 0);
    const int L = is64 ? (int)((const long long*)in_lens_raw)[n] : w32[n];

    const int*   a  = g_amax + n * T_DIM;
    const float* mv = g_maxv + n * T_DIM;

    // ---- single vector load of this thread's pair ----
    const int t0 = 2 * tid;
    const int2   aa = reinterpret_cast<const int2*>(a)[tid];
    const float2 mm = reinterpret_cast<const float2*>(mv)[tid];

    // prev element for t0: element t0-1 = previous thread's aa.y.
    int prev = __shfl_up_sync(0xffffffffu, aa.y, 1);
    if (lane == 0) prev = (tid == 0) ? -123 : a[t0 - 1];  // warp boundary / t=0

    const bool k0 = (aa.x != BLANK) && (aa.x != prev) && (t0     < L);
    const bool k1 = (aa.y != BLANK) && (aa.y != aa.x) && (t0 + 1 < L);
    const int  cnt = (int)k0 + (int)k1;

    // ---- max_total partial (fold into the same pass) ----
    float loc = ((t0 < L) ? mm.x : 0.f) + ((t0 + 1 < L) ? mm.y : 0.f);

    // ---- inclusive warp scan of cnt; warp reduce of loc ----
    int inc = cnt;
#pragma unroll
    for (int off = 1; off < 32; off <<= 1) {
        int v = __shfl_up_sync(0xffffffffu, inc, off);
        if (lane >= off) inc += v;
        loc += __shfl_down_sync(0xffffffffu, loc, off);  // lane0 holds warp sum
    }

    __shared__ int   s_wcnt[32];   // exclusive prefix of warp totals (after scan)
    __shared__ float s_wsum[32];
    if (lane == 31) s_wcnt[wid] = inc;      // warp total
    if (lane == 0)  s_wsum[wid] = loc;      // warp sum
    __syncthreads();

    if (wid == 0) {
        // scan 32 warp totals (exclusive), reduce 32 warp sums
        int v = s_wcnt[lane];
        int inc2 = v;
#pragma unroll
        for (int off = 1; off < 32; off <<= 1) {
            int u = __shfl_up_sync(0xffffffffu, inc2, off);
            if (lane >= off) inc2 += u;
        }
        s_wcnt[lane] = inc2 - v;            // exclusive warp offset

        float fs = s_wsum[lane];
#pragma unroll
        for (int off = 16; off; off >>= 1)
            fs += __shfl_down_sync(0xffffffffu, fs, off);

        if (lane == 31) out[N_DIM + (size_t)T_DIM * N_DIM + n] = (float)inc2;  // out_lens
        if (lane == 0)  out[n] = fs;                                           // max_total
    }
    __syncthreads();

    // ---- scatter kept tokens ----
    float* paths = out + N_DIM;
    int pos = s_wcnt[wid] + (inc - cnt);    // exclusive start for this thread
    if (k0) { paths[pos * N_DIM + n] = (float)aa.x; pos++; }
    if (k1) { paths[pos * N_DIM + n] = (float)aa.y; }
}

// ---------------------------------------------------------------------------
extern "C" void kernel_launch(void* const* d_in, const int* in_sizes, int n_in,
                              void* d_out, int out_size)
{
    const float* logits = (const float*)d_in[0];
    const void*  lens   = d_in[1];
    float* out = (float*)d_out;

    (void)in_sizes; (void)n_in; (void)out_size;

    // Kernel 1: T*N = 65536 warps -> 8192 blocks of 256 threads
    ctc_rowmax_kernel<<<(T_DIM * N_DIM) / 8, 256>>>(logits, out + N_DIM);
    // Kernel 2: one 1024-thread block per batch row, single pass
    ctc_scan_kernel<<<N_DIM, 1024>>>(lens, out);
}

// round 13
// speedup vs baseline: 1.1791x; 1.0344x over previous
#include <cuda_runtime.h>

// CTC greedy search — two kernels (proven structure; R12 best: 47.14us).
// R13: K1 warp max/argmax reduction via REDUX (__reduce_max/min_sync) on a
// monotonic float key — replaces a 22-instr shuffle tree with ~8 instrs.
//   logits: (T=2048, N=32, V=1024) float32, batch_first = False
//   in_lens: (N,) int (int32 or int64 — detected at runtime)
// Output (float32): [ max_total (N) | paths (T*N, t*N+n) | out_lens (N) ]

#define T_DIM 2048
#define N_DIM 32
#define V_DIM 1024
#define BLANK 1023   // (-1 + V) % V

// Scratch (allocation-free rule: __device__ globals). n-major for kernel2 coalescing.
__device__ int   g_amax[(size_t)T_DIM * N_DIM];
__device__ float g_maxv[(size_t)T_DIM * N_DIM];

// Monotonic (order-preserving) float->uint key and inverse.
__device__ __forceinline__ unsigned fkey(float x) {
    unsigned u = __float_as_uint(x);
    return u ^ (((int)u >> 31) | 0x80000000u);   // pos: flip sign bit; neg: flip all
}
__device__ __forceinline__ float unfkey(unsigned k) {
    unsigned u = (k & 0x80000000u) ? (k ^ 0x80000000u) : ~k;
    return __uint_as_float(u);
}

// ---------------------------------------------------------------------------
// Kernel 1: one warp per (t, n) row of V=1024 logits (~6.8 TB/s).
// ---------------------------------------------------------------------------
__global__ void __launch_bounds__(256) ctc_rowmax_kernel(
    const float* __restrict__ logits, float* __restrict__ out_paths)
{
    const int warp_id = (blockIdx.x * 256 + threadIdx.x) >> 5;  // = t*N + n
    const int lane = threadIdx.x & 31;

    const float4* row =
        reinterpret_cast<const float4*>(logits) + (size_t)warp_id * (V_DIM / 4);

    float4 v[8];
#pragma unroll
    for (int k = 0; k < 8; k++) v[k] = __ldcs(&row[lane + 32 * k]);  // evict-first

    // per-lane max + first-occurrence argmax (indices visited in increasing order)
    float m = -1e30f; int mi = 0;
#pragma unroll
    for (int k = 0; k < 8; k++) {
        const int base = (lane + 32 * k) * 4;
        float x;
        x = v[k].x; if (x > m) { m = x; mi = base;     }
        x = v[k].y; if (x > m) { m = x; mi = base + 1; }
        x = v[k].z; if (x > m) { m = x; mi = base + 2; }
        x = v[k].w; if (x > m) { m = x; mi = base + 3; }
    }

    // warp max via REDUX on monotonic key; first-occurrence tie-break via
    // REDUX-min over tied lanes' indices.
    const unsigned myKey = fkey(m);
    const unsigned wKey  = __reduce_max_sync(0xffffffffu, myKey);
    mi = __reduce_min_sync(0xffffffffu, (myKey == wKey) ? (unsigned)mi : 0x7fffffffu);
    m  = unfkey(wKey);

    // sum exp(x - m); MUFU throughput hides under HBM stream
    float s = 0.f;
#pragma unroll
    for (int k = 0; k < 8; k++) {
        s += __expf(v[k].x - m) + __expf(v[k].y - m)
           + __expf(v[k].z - m) + __expf(v[k].w - m);
    }
#pragma unroll
    for (int off = 16; off; off >>= 1) s += __shfl_down_sync(0xffffffffu, s, off);

    if (lane == 0) {
        const int t = warp_id >> 5;          // / N_DIM
        const int n = warp_id & 31;
        g_amax[n * T_DIM + t] = mi;
        g_maxv[n * T_DIM + t] = -logf(s);    // max over V of log_softmax
        out_paths[warp_id] = (float)mi;      // masked_scatter default region
    }
}

// ---------------------------------------------------------------------------
// Kernel 2 (single-pass, FROZEN from R2/R12): one 1024-thread block per row n.
// ---------------------------------------------------------------------------
__global__ void __launch_bounds__(1024) ctc_scan_kernel(
    const void* __restrict__ in_lens_raw, float* __restrict__ out)
{
    const int n    = blockIdx.x;
    const int tid  = threadIdx.x;     // 0..1023
    const int lane = tid & 31;
    const int wid  = tid >> 5;        // 0..31

    // dtype-robust in_lens read: values are in [1, T] (never 0). If the buffer
    // is int64 (LE), every high 32-bit word is 0; if int32, word[1] >= 1.
    const int* w32 = (const int*)in_lens_raw;
    const bool is64 = (w32[1] == 0);
    const int L = is64 ? (int)((const long long*)in_lens_raw)[n] : w32[n];

    const int*   a  = g_amax + n * T_DIM;
    const float* mv = g_maxv + n * T_DIM;

    // ---- single vector load of this thread's pair ----
    const int t0 = 2 * tid;
    const int2   aa = reinterpret_cast<const int2*>(a)[tid];
    const float2 mm = reinterpret_cast<const float2*>(mv)[tid];

    // prev element for t0: element t0-1 = previous thread's aa.y.
    int prev = __shfl_up_sync(0xffffffffu, aa.y, 1);
    if (lane == 0) prev = (tid == 0) ? -123 : a[t0 - 1];  // warp boundary / t=0

    const bool k0 = (aa.x != BLANK) && (aa.x != prev) && (t0     < L);
    const bool k1 = (aa.y != BLANK) && (aa.y != aa.x) && (t0 + 1 < L);
    const int  cnt = (int)k0 + (int)k1;

    // ---- max_total partial (fold into the same pass) ----
    float loc = ((t0 < L) ? mm.x : 0.f) + ((t0 + 1 < L) ? mm.y : 0.f);

    // ---- inclusive warp scan of cnt; warp reduce of loc ----
    int inc = cnt;
#pragma unroll
    for (int off = 1; off < 32; off <<= 1) {
        int v = __shfl_up_sync(0xffffffffu, inc, off);
        if (lane >= off) inc += v;
        loc += __shfl_down_sync(0xffffffffu, loc, off);  // lane0 holds warp sum
    }

    __shared__ int   s_wcnt[32];   // exclusive prefix of warp totals (after scan)
    __shared__ float s_wsum[32];
    if (lane == 31) s_wcnt[wid] = inc;      // warp total
    if (lane == 0)  s_wsum[wid] = loc;      // warp sum
    __syncthreads();

    if (wid == 0) {
        // scan 32 warp totals (exclusive), reduce 32 warp sums
        int v = s_wcnt[lane];
        int inc2 = v;
#pragma unroll
        for (int off = 1; off < 32; off <<= 1) {
            int u = __shfl_up_sync(0xffffffffu, inc2, off);
            if (lane >= off) inc2 += u;
        }
        s_wcnt[lane] = inc2 - v;            // exclusive warp offset

        float fs = s_wsum[lane];
#pragma unroll
        for (int off = 16; off; off >>= 1)
            fs += __shfl_down_sync(0xffffffffu, fs, off);

        if (lane == 31) out[N_DIM + (size_t)T_DIM * N_DIM + n] = (float)inc2;  // out_lens
        if (lane == 0)  out[n] = fs;                                           // max_total
    }
    __syncthreads();

    // ---- scatter kept tokens ----
    float* paths = out + N_DIM;
    int pos = s_wcnt[wid] + (inc - cnt);    // exclusive start for this thread
    if (k0) { paths[pos * N_DIM + n] = (float)aa.x; pos++; }
    if (k1) { paths[pos * N_DIM + n] = (float)aa.y; }
}

// ---------------------------------------------------------------------------
extern "C" void kernel_launch(void* const* d_in, const int* in_sizes, int n_in,
                              void* d_out, int out_size)
{
    const float* logits = (const float*)d_in[0];
    const void*  lens   = d_in[1];
    float* out = (float*)d_out;

    (void)in_sizes; (void)n_in; (void)out_size;

    // Kernel 1: T*N = 65536 warps -> 8192 blocks of 256 threads
    ctc_rowmax_kernel<<<(T_DIM * N_DIM) / 8, 256>>>(logits, out + N_DIM);
    // Kernel 2: one 1024-thread block per batch row, single pass
    ctc_scan_kernel<<<N_DIM, 1024>>>(lens, out);
}